// round 7
// baseline (speedup 1.0000x reference)
#include <cuda_runtime.h>
#include <math.h>

#define NUM_NEURONS 2048
#define D_MODEL     1024
#define BATCH       64
#define KSPLIT      32
#define KCHUNK      128
#define DCHUNK      128

// Scratch (static device globals — no runtime allocation)
__device__ __align__(16) float g_xT[D_MODEL * BATCH];             // x transposed [d][b]
__device__ __align__(16) float g_S[2 * NUM_NEURONS * BATCH];      // sums [k][b]: cos rows then sin rows
__device__ __align__(16) float g_part[KSPLIT * BATCH * D_MODEL];  // GEMM partials (8MB)

// ---------------------------------------------------------------------------
// Transpose x -> [d][b] so main-kernel shared stage is coalesced.
// ---------------------------------------------------------------------------
__global__ void prep_x(const float* __restrict__ x) {
    int i = blockIdx.x * 256 + threadIdx.x;   // 65536 total
    g_xT[(i & 1023) * BATCH + (i >> 10)] = x[i];
}

// ---------------------------------------------------------------------------
// FMA-pipe sincos: quadrant reduction via magic-number round; Taylor deg7/deg6
// on u in [-0.5,0.5] quarter-turns. Abs err <= ~4e-6. (R3-proven variant.)
// ---------------------------------------------------------------------------
__device__ __forceinline__ void sincos_poly(float th, float& s_out, float& c_out) {
    const float TWO_OVER_PI = 0.636619772f;
    const float MAGIC = 12582912.0f;       // 1.5 * 2^23
    float w   = th * TWO_OVER_PI;
    float big = w + MAGIC;                 // round-to-nearest-even
    int   qi  = __float_as_int(big);       // low mantissa bits = q mod 4
    float r   = big - MAGIC;
    float u   = w - r;                     // [-0.5, 0.5]
    float u2  = u * u;
    float sp  = fmaf(u2, fmaf(u2, fmaf(u2, -4.6817541e-3f, 7.9692626e-2f),
                              -6.4596410e-1f), 1.57079633f) * u;   // sin(u*pi/2)
    float cp  = fmaf(u2, fmaf(u2, fmaf(u2, -2.0864648e-2f, 2.5369510e-1f),
                              -1.2337006f), 1.0f);                 // cos(u*pi/2)
    float ss = (qi & 1) ? cp : sp;
    float cc = (qi & 1) ? sp : cp;
    if (qi & 2)       ss = -ss;
    if ((qi + 1) & 2) cc = -cc;
    s_out = ss; c_out = cc;
}

// ---------------------------------------------------------------------------
// Main: per CTA, 2 neurons x all 64 batches; d-loop staged through shared.
// Dual-path sincos: 3/4 MUFU, 1/4 FMA-pipe polynomial (R3-proven balance;
// R4/R6 rebalances both regressed).
// ---------------------------------------------------------------------------
__global__ __launch_bounds__(128) void resonant_main(const float* __restrict__ t,
                                                     const float* __restrict__ W,
                                                     const float* __restrict__ Bp) {
    __shared__ float  x_sh[DCHUNK][BATCH];   // 32 KB, lane=b conflict-free
    __shared__ float2 rB_sh[2][DCHUNK];      // 2 KB, warp-broadcast reads

    int tid = threadIdx.x;
    int b   = tid & 63;
    int nl  = tid >> 6;
    int n0  = blockIdx.x * 2;

    float tb = t[b];
    float cs = 0.0f, sn = 0.0f;

    for (int d0 = 0; d0 < D_MODEL; d0 += DCHUNK) {
        float4*       xs4 = reinterpret_cast<float4*>(&x_sh[0][0]);
        const float4* xg4 = reinterpret_cast<const float4*>(g_xT + d0 * BATCH);
        #pragma unroll
        for (int i = 0; i < (DCHUNK * BATCH / 4) / 128; i++)
            xs4[tid + i * 128] = xg4[tid + i * 128];
        {
            float w0 = W [(n0 + 0) * D_MODEL + d0 + tid];
            float p0 = Bp[(n0 + 0) * D_MODEL + d0 + tid];
            rB_sh[0][tid] = make_float2(__fdividef(1.0f, 1.0f + fabsf(w0)), p0);
            float w1 = W [(n0 + 1) * D_MODEL + d0 + tid];
            float p1 = Bp[(n0 + 1) * D_MODEL + d0 + tid];
            rB_sh[1][tid] = make_float2(__fdividef(1.0f, 1.0f + fabsf(w1)), p1);
        }
        __syncthreads();

        #pragma unroll
        for (int dd = 0; dd < DCHUNK; dd += 4) {
            #pragma unroll
            for (int j = 0; j < 3; j++) {          // 3 MUFU-path elements
                float2 rb = rB_sh[nl][dd + j];
                float th  = fmaf(x_sh[dd + j][b], rb.x, rb.y) + tb;
                float s, c;
                __sincosf(th, &s, &c);
                cs += c; sn += s;
            }
            {                                       // 1 FMA-pipe poly element
                float2 rb = rB_sh[nl][dd + 3];
                float th  = fmaf(x_sh[dd + 3][b], rb.x, rb.y) + tb;
                float s, c;
                sincos_poly(th, s, c);
                cs += c; sn += s;
            }
        }
        __syncthreads();
    }

    int n = n0 + nl;
    g_S[n * BATCH + b]                 = cs;  // cos row: k = n
    g_S[(n + NUM_NEURONS) * BATCH + b] = sn;  // sin row: k = n + 2048
}

// ---------------------------------------------------------------------------
// GEMM: C[b][j] = sum_k S[k][b] * Pcat[j][k], K=4096 split 32 ways.
// 64x64 CTA tile, 128 threads, 4(b)x8(j) per-thread tile: 3 LDS.128 per
// 32 FFMA -> FMA-pipe bound (the 256-thr/4x4 version was LDS co-bound).
// Register double-buffered global staging. Partials disjoint -> no atomics.
// ---------------------------------------------------------------------------
__global__ __launch_bounds__(128) void gemm_kernel(const float* __restrict__ Pr,
                                                   const float* __restrict__ Pi) {
    __shared__ float S_sh[32][64];
    __shared__ float P_sh[32][68];   // padded rows, 16B-aligned

    int tid = threadIdx.x;
    int tx  = tid & 7;    // j groups of 8 (0..7)
    int ty  = tid >> 3;   // b groups of 4 (0..15)
    int j0  = blockIdx.x * 64;
    int k0  = blockIdx.y * KCHUNK;

    const float* P     = (k0 < NUM_NEURONS) ? Pr : Pi;
    int          kbase = (k0 < NUM_NEURONS) ? k0 : k0 - NUM_NEURONS;

    // staging ownership
    // S: 32x64 = 512 float4, 128 threads -> 4 each (tid, +128, +256, +384)
    // P: 64 j-rows, 2 threads per row, 16 contiguous k each (4 float4)
    int jl  = tid >> 1;           // 0..63
    int kk0 = (tid & 1) * 16;     // 0 or 16

    float4 sR[4], pR[4];
    {   // preload chunk 0
        const float4* sg = reinterpret_cast<const float4*>(g_S + k0 * BATCH);
        #pragma unroll
        for (int q = 0; q < 4; q++) sR[q] = sg[tid + q * 128];
        const float4* pg = reinterpret_cast<const float4*>(
            P + (j0 + jl) * NUM_NEURONS + kbase + kk0);
        #pragma unroll
        for (int q = 0; q < 4; q++) pR[q] = pg[q];
    }

    float acc[4][8] = {};

    #pragma unroll
    for (int kc = 0; kc < KCHUNK; kc += 32) {
        __syncthreads();
        // commit staged regs to smem
        #pragma unroll
        for (int q = 0; q < 4; q++)
            reinterpret_cast<float4*>(&S_sh[0][0])[tid + q * 128] = sR[q];
        #pragma unroll
        for (int q = 0; q < 4; q++) {
            P_sh[kk0 + q * 4 + 0][jl] = pR[q].x;
            P_sh[kk0 + q * 4 + 1][jl] = pR[q].y;
            P_sh[kk0 + q * 4 + 2][jl] = pR[q].z;
            P_sh[kk0 + q * 4 + 3][jl] = pR[q].w;
        }
        __syncthreads();

        if (kc + 32 < KCHUNK) {   // prefetch next chunk into registers
            const float4* sg = reinterpret_cast<const float4*>(g_S + (k0 + kc + 32) * BATCH);
            #pragma unroll
            for (int q = 0; q < 4; q++) sR[q] = sg[tid + q * 128];
            const float4* pg = reinterpret_cast<const float4*>(
                P + (j0 + jl) * NUM_NEURONS + kbase + kc + 32 + kk0);
            #pragma unroll
            for (int q = 0; q < 4; q++) pR[q] = pg[q];
        }

        #pragma unroll
        for (int kk = 0; kk < 32; kk++) {
            float4 a  = *reinterpret_cast<const float4*>(&S_sh[kk][ty * 4]);
            float4 p0 = *reinterpret_cast<const float4*>(&P_sh[kk][tx * 8]);
            float4 p1 = *reinterpret_cast<const float4*>(&P_sh[kk][tx * 8 + 4]);
            float av[4] = {a.x, a.y, a.z, a.w};
            float pv[8] = {p0.x, p0.y, p0.z, p0.w, p1.x, p1.y, p1.z, p1.w};
            #pragma unroll
            for (int ii = 0; ii < 4; ii++)
                #pragma unroll
                for (int jj = 0; jj < 8; jj++)
                    acc[ii][jj] = fmaf(av[ii], pv[jj], acc[ii][jj]);
        }
    }

    float* dst = g_part + blockIdx.y * (BATCH * D_MODEL);
    #pragma unroll
    for (int ii = 0; ii < 4; ii++) {
        float* row = dst + (ty * 4 + ii) * D_MODEL + j0 + tx * 8;
        *reinterpret_cast<float4*>(row)     = make_float4(acc[ii][0], acc[ii][1],
                                                          acc[ii][2], acc[ii][3]);
        *reinterpret_cast<float4*>(row + 4) = make_float4(acc[ii][4], acc[ii][5],
                                                          acc[ii][6], acc[ii][7]);
    }
}

// ---------------------------------------------------------------------------
// Epilogue: reduce K-split partials + SiLU. R3-proven config: scalar loads,
// 256 CTAs x 256 threads (all float4 variants regressed: R4/R5).
// ---------------------------------------------------------------------------
__global__ __launch_bounds__(256) void epilogue(float* __restrict__ out) {
    int i = blockIdx.x * 256 + threadIdx.x;   // 65536 outputs
    float s = 0.0f;
    #pragma unroll
    for (int ks = 0; ks < KSPLIT; ks++)
        s += g_part[ks * (BATCH * D_MODEL) + i];
    out[i] = s / (1.0f + expf(-s));           // silu
}

// ---------------------------------------------------------------------------
// Inputs: x, t, W, B_p, proj_real_w, proj_imag_w, sin_table, cos_table.
// Tables unused: HW sincos / poly within ~4e-6 abs of the LUT-lerp reference.
// Single stream (R2: chunked multi-stream overlap destroyed occupancy).
// ---------------------------------------------------------------------------
extern "C" void kernel_launch(void* const* d_in, const int* in_sizes, int n_in,
                              void* d_out, int out_size) {
    const float* x  = (const float*)d_in[0];
    const float* t  = (const float*)d_in[1];
    const float* W  = (const float*)d_in[2];
    const float* Bp = (const float*)d_in[3];
    const float* Pr = (const float*)d_in[4];
    const float* Pi = (const float*)d_in[5];
    float* out = (float*)d_out;

    prep_x<<<(BATCH * D_MODEL + 255) / 256, 256>>>(x);
    resonant_main<<<NUM_NEURONS / 2, 128>>>(t, W, Bp);
    dim3 gg(D_MODEL / 64, KSPLIT);
    gemm_kernel<<<gg, 128>>>(Pr, Pi);
    epilogue<<<(BATCH * D_MODEL + 255) / 256, 256>>>(out);
}